// round 9
// baseline (speedup 1.0000x reference)
#include <cuda_runtime.h>
#include <math.h>

#define NB 32
#define Wd 512
#define Hd 512
#define SEG (Hd*Wd)              // 262144 per image
#define NTOT (NB*SEG)            // 8388608
#define TPB 256
#define IPT 16
#define BLK_ITEMS (TPB*IPT)      // 4096
#define NBLOCKS (NTOT/BLK_ITEMS) // 2048
#define BLKS_PER_SEG (SEG/BLK_ITEMS) // 64
#define NBINS 65536

// ---------------- scratch (static device globals; no allocation) -------------
__device__ unsigned g_keysA[NTOT];
__device__ unsigned g_keysB[NTOT];
__device__ unsigned g_hist[NB*NBINS];    // per-image 16-bit-digit histogram -> bases
__device__ unsigned g_chunkPos[NBLOCKS];
__device__ unsigned g_chunkOff[NBLOCKS];
__device__ double g_bce, g_bnd;
__device__ double g_pt[NB], g_pd[NB], g_gts[NB];
__device__ double g_lov[NB];

// ---------------- helpers ----------------------------------------------------
__device__ __forceinline__ float warpReduceF(float v) {
    #pragma unroll
    for (int o = 16; o; o >>= 1) v += __shfl_down_sync(0xFFFFFFFFu, v, o);
    return v;
}

__device__ __forceinline__ float blockReduceF(float v) {
    __shared__ float s[8];
    int lane = threadIdx.x & 31, wid = threadIdx.x >> 5;
    v = warpReduceF(v);
    if (lane == 0) s[wid] = v;
    __syncthreads();
    v = (threadIdx.x < 8) ? s[threadIdx.x] : 0.f;
    if (wid == 0) v = warpReduceF(v);
    __syncthreads();
    return v;  // valid on thread 0
}

// 256-thread exclusive scan (one int per thread)
__device__ __forceinline__ int blockExclScanI(int v) {
    int lane = threadIdx.x & 31, wid = threadIdx.x >> 5;
    int inc = v;
    #pragma unroll
    for (int o = 1; o < 32; o <<= 1) {
        int n = __shfl_up_sync(0xFFFFFFFFu, inc, o);
        if (lane >= o) inc += n;
    }
    __shared__ int ws[8];
    if (lane == 31) ws[wid] = inc;
    __syncthreads();
    if (threadIdx.x < 8) {
        int s = ws[threadIdx.x]; int i2 = s;
        #pragma unroll
        for (int o = 1; o < 8; o <<= 1) {
            int n = __shfl_up_sync(0xFFu, i2, o);
            if ((int)threadIdx.x >= o) i2 += n;
        }
        ws[threadIdx.x] = i2 - s;
    }
    __syncthreads();
    int r = inc - v + ws[wid];
    __syncthreads();
    return r;
}

// descending-float order == ascending-uint order; label y in mantissa LSB
__device__ __forceinline__ unsigned encodeKey(float e, int y) {
    unsigned u = (__float_as_uint(e) & ~1u) | (unsigned)y;
    unsigned o = (u & 0x80000000u) ? ~u : (u ^ 0x80000000u);
    return ~o;
}
__device__ __forceinline__ unsigned decodeBits(unsigned key) {
    unsigned o = ~key;
    return (o & 0x80000000u) ? (o ^ 0x80000000u) : ~o;
}

// ---------------- kernels ----------------------------------------------------
__global__ void k_init() {
    int t = blockIdx.x * blockDim.x + threadIdx.x;
    uint4* h4 = (uint4*)g_hist;
    int n4 = NB*NBINS/4;
    for (int i = t; i < n4; i += gridDim.x * blockDim.x)
        h4[i] = make_uint4(0u, 0u, 0u, 0u);
    if (t < NBLOCKS) g_chunkPos[t] = 0;
    if (t < NB) { g_pt[t] = 0.0; g_pd[t] = 0.0; g_gts[t] = 0.0; g_lov[t] = 0.0; }
    if (t == NB) { g_bce = 0.0; g_bnd = 0.0; }
}

// Fused: BCE + boundary BCE + Dice sums + key build + 16-bit-digit histogram (RED).
// Each thread owns 16 CONTIGUOUS pixels (one row span); stencil via float4 loads.
__global__ __launch_bounds__(TPB) void k_main(const float* __restrict__ logits,
                                              const float* __restrict__ tgt) {
    int blk = blockIdx.x, t = threadIdx.x;
    int seg = blk >> 6;
    int base = blk * BLK_ITEMS;

    __shared__ unsigned sh_keys[BLK_ITEMS];
    unsigned* hist = g_hist + (seg << 16);

    float aB = 0.f, aW = 0.f, aPt = 0.f, aPd = 0.f, aY = 0.f;

    int q0 = base + t * 16;           // first pixel of this thread (global index)
    int pos0 = q0 - seg * SEG;
    int h = pos0 >> 9;
    int w0 = pos0 & 511;
    bool hasTop = (h > 0), hasBot = (h < Hd - 1);

    const float4* lg4 = (const float4*)logits;
    const float4* tg4 = (const float4*)tgt;

    #pragma unroll
    for (int c = 0; c < 4; c++) {
        int p = q0 + c * 4;
        int w = w0 + c * 4;
        float4 lx = lg4[p >> 2];

        float rv[3][6];
        #pragma unroll
        for (int r = 0; r < 3; r++) {
            int dr = r - 1;
            bool rowok = (dr == 0) || (dr < 0 ? hasTop : hasBot);
            int rp = p + dr * Wd;
            float4 cv = rowok ? tg4[rp >> 2] : make_float4(0.f, 0.f, 0.f, 0.f);
            rv[r][1] = cv.x; rv[r][2] = cv.y; rv[r][3] = cv.z; rv[r][4] = cv.w;
            rv[r][0] = (rowok && w > 0)        ? __ldg(&tgt[rp - 1]) : 0.f;
            rv[r][5] = (rowok && w + 4 < Wd)   ? __ldg(&tgt[rp + 4]) : 0.f;
        }

        float xs[4] = {lx.x, lx.y, lx.z, lx.w};
        #pragma unroll
        for (int i = 0; i < 4; i++) {
            float x = xs[i];
            float y = rv[1][i + 1];
            float ax = fabsf(x);
            float bce = fmaxf(x, 0.f) - x * y + log1pf(expf(-ax));
            float pr = 1.f / (1.f + expf(-x));
            float cnt = rv[0][i] + rv[0][i+1] + rv[0][i+2]
                      + rv[1][i] + rv[1][i+1] + rv[1][i+2]
                      + rv[2][i] + rv[2][i+1] + rv[2][i+2];
            float wt = (cnt > 0.5f && cnt < 8.5f) ? 3.0f : 1.0f;

            aB += bce; aW += bce * wt; aPt += pr * y; aPd += pr + y; aY += y;

            unsigned key = encodeKey(fmaf(-x, 2.f*y - 1.f, 1.f), (int)y);
            sh_keys[t * 16 + c * 4 + i] = key;
            atomicAdd(&hist[key >> 16], 1u);   // no return -> RED
        }
    }
    __syncthreads();

    // coalesced key write-out
    #pragma unroll
    for (int j = 0; j < IPT; j++)
        g_keysA[base + j*TPB + t] = sh_keys[j*TPB + t];

    float r;
    r = blockReduceF(aB);  if (t == 0) atomicAdd(&g_bce, (double)r);
    r = blockReduceF(aW);  if (t == 0) atomicAdd(&g_bnd, (double)r);
    r = blockReduceF(aPt); if (t == 0) atomicAdd(&g_pt[seg], (double)r);
    r = blockReduceF(aPd); if (t == 0) atomicAdd(&g_pd[seg], (double)r);
    r = blockReduceF(aY);  if (t == 0) atomicAdd(&g_gts[seg], (double)r);
}

// In-place exclusive scan of the 65536-bin histogram of one image.
// grid = NB, block = 256; thread t owns bins [t*256, (t+1)*256).
__global__ __launch_bounds__(TPB) void k_pscan() {
    int seg = blockIdx.x, t = threadIdx.x;
    uint4* h4 = (uint4*)(g_hist + (seg << 16) + t * 256);
    unsigned tot = 0;
    #pragma unroll
    for (int q = 0; q < 64; q++) {
        uint4 v = h4[q];
        tot += v.x + v.y + v.z + v.w;
    }
    unsigned run = (unsigned)(seg * SEG) + (unsigned)blockExclScanI((int)tot);
    #pragma unroll
    for (int q = 0; q < 64; q++) {
        uint4 v = h4[q];
        uint4 o;
        o.x = run; run += v.x;
        o.y = run; run += v.y;
        o.z = run; run += v.z;
        o.w = run; run += v.w;
        h4[q] = o;
    }
}

// Single-pass counting-sort scatter: rank by atomicAdd on the bin cursor.
// Within-bin order is arrival order (irrelevant: equal top-16-bit keys).
__global__ __launch_bounds__(TPB) void k_scatter() {
    int blk = blockIdx.x, t = threadIdx.x;
    int seg = blk >> 6;
    const uint4* in4 = (const uint4*)(g_keysA + blk * BLK_ITEMS);
    unsigned* hist = g_hist + (seg << 16);

    #pragma unroll
    for (int j = 0; j < IPT/4; j++) {
        uint4 k = in4[j*TPB + t];
        unsigned p0 = atomicAdd(&hist[k.x >> 16], 1u);
        unsigned p1 = atomicAdd(&hist[k.y >> 16], 1u);
        unsigned p2 = atomicAdd(&hist[k.z >> 16], 1u);
        unsigned p3 = atomicAdd(&hist[k.w >> 16], 1u);
        g_keysB[p0] = k.x;
        g_keysB[p1] = k.y;
        g_keysB[p2] = k.z;
        g_keysB[p3] = k.w;
    }
}

__global__ __launch_bounds__(TPB) void k_chunkpos() {
    int blk = blockIdx.x, t = threadIdx.x;
    const uint4* p4 = (const uint4*)(g_keysB + blk * BLK_ITEMS);
    int s = 0;
    #pragma unroll
    for (int j = 0; j < IPT/4; j++) {
        uint4 k = p4[j*TPB + t];
        s += (int)(decodeBits(k.x) & 1u) + (int)(decodeBits(k.y) & 1u)
           + (int)(decodeBits(k.z) & 1u) + (int)(decodeBits(k.w) & 1u);
    }
    float r = blockReduceF((float)s);
    if (t == 0) g_chunkPos[blk] = (unsigned)r;
}

__global__ void k_chunkscan() {
    int s = threadIdx.x;  // one thread per image
    if (s >= NB) return;
    unsigned run = 0;
    for (int c = 0; c < BLKS_PER_SEG; c++) {
        g_chunkOff[s*BLKS_PER_SEG + c] = run;
        run += g_chunkPos[s*BLKS_PER_SEG + c];
    }
}

__global__ __launch_bounds__(TPB) void k_lovasz() {
    int blk = blockIdx.x, t = threadIdx.x;
    int seg = blk / BLKS_PER_SEG;
    int base = blk * BLK_ITEMS;

    unsigned u[IPT]; int yv[IPT];
    const uint4* p4 = (const uint4*)(g_keysB + base + t*IPT);
    int lsum = 0;
    #pragma unroll
    for (int q = 0; q < IPT/4; q++) {
        uint4 kk = p4[q];
        unsigned arr[4] = {kk.x, kk.y, kk.z, kk.w};
        #pragma unroll
        for (int r = 0; r < 4; r++) {
            unsigned uu = decodeBits(arr[r]);
            u[q*4 + r] = uu;
            yv[q*4 + r] = (int)(uu & 1u);
            lsum += (int)(uu & 1u);
        }
    }

    int excl = blockExclScanI(lsum);
    float gts = (float)g_gts[seg];
    float P = (float)(g_chunkOff[blk] + (unsigned)excl); // positives strictly before
    int pos0 = (blk % BLKS_PER_SEG) * BLK_ITEMS + t*IPT;

    float acc = 0.f;
    #pragma unroll
    for (int j = 0; j < IPT; j++) {
        float e = __uint_as_float(u[j]);
        int y = yv[j];
        if (e > 0.f) {
            float Uprev = gts + (float)(pos0 + j) - P;
            float grad = y ? (1.0f / Uprev)
                           : ((gts - P) / (Uprev * (Uprev + 1.0f)));
            acc += e * grad;
        }
        P += (float)y;
    }
    float r = blockReduceF(acc);
    if (t == 0) atomicAdd(&g_lov[seg], (double)r);
}

__global__ void k_final(float* out, int out_size) {
    if (threadIdx.x == 0 && blockIdx.x == 0) {
        double dice = 0.0;
        for (int b = 0; b < NB; b++) dice += (2.0 * g_pt[b]) / (g_pd[b] + 1e-7);
        double lov = 0.0;
        for (int b = 0; b < NB; b++) lov += g_lov[b];
        double loss = 0.3 * (g_bce / (double)NTOT)
                    + 0.3 * (1.0 - dice / (double)NB)
                    + 0.2 * (g_bnd / (double)NTOT)
                    + 0.2 * (lov / (double)NB);
        for (int i = 0; i < out_size; i++) out[i] = (float)loss;
    }
}

// ---------------- launch ------------------------------------------------------
extern "C" void kernel_launch(void* const* d_in, const int* in_sizes, int n_in,
                              void* d_out, int out_size) {
    const float* logits = (const float*)d_in[0];
    const float* tgt    = (const float*)d_in[1];
    float* out = (float*)d_out;

    k_init<<<1024, 256>>>();
    k_main<<<NBLOCKS, TPB>>>(logits, tgt);
    k_pscan<<<NB, 256>>>();
    k_scatter<<<NBLOCKS, TPB>>>();
    k_chunkpos<<<NBLOCKS, TPB>>>();
    k_chunkscan<<<1, 32>>>();
    k_lovasz<<<NBLOCKS, TPB>>>();
    k_final<<<1, 32>>>(out, out_size);
}

// round 10
// speedup vs baseline: 2.0073x; 2.0073x over previous
#include <cuda_runtime.h>
#include <math.h>

#define NB 32
#define Wd 512
#define Hd 512
#define SEG (Hd*Wd)              // 262144 per image
#define NTOT (NB*SEG)            // 8388608
#define TPB 256
#define IPT 16
#define BLK_ITEMS (TPB*IPT)      // 4096
#define NBLOCKS (NTOT/BLK_ITEMS) // 2048
#define NBINS 32768              // top-15 bins of positive-e floats
#define BINS_PER_T (NBINS/TPB)   // 128

// ---------------- scratch (static device globals; no allocation) -------------
// per-image, per-bin: {cntPos, sumEpos, cntNeg, sumEneg}  (16 MB total)
// zero at module load; k_bins restores zeros after reading (graph-replay safe).
__device__ float g_acc[NB*NBINS*4];
__device__ double g_bce, g_bnd;
__device__ double g_pt[NB], g_pd[NB], g_gts[NB];
__device__ double g_lov[NB];

// ---------------- helpers ----------------------------------------------------
__device__ __forceinline__ float warpReduceF(float v) {
    #pragma unroll
    for (int o = 16; o; o >>= 1) v += __shfl_down_sync(0xFFFFFFFFu, v, o);
    return v;
}

__device__ __forceinline__ float blockReduceF(float v) {
    __shared__ float s[8];
    int lane = threadIdx.x & 31, wid = threadIdx.x >> 5;
    v = warpReduceF(v);
    if (lane == 0) s[wid] = v;
    __syncthreads();
    v = (threadIdx.x < 8) ? s[threadIdx.x] : 0.f;
    if (wid == 0) v = warpReduceF(v);
    __syncthreads();
    return v;  // valid on thread 0
}

// 256-thread exclusive scan (one int per thread)
__device__ __forceinline__ int blockExclScanI(int v) {
    int lane = threadIdx.x & 31, wid = threadIdx.x >> 5;
    int inc = v;
    #pragma unroll
    for (int o = 1; o < 32; o <<= 1) {
        int n = __shfl_up_sync(0xFFFFFFFFu, inc, o);
        if (lane >= o) inc += n;
    }
    __shared__ int ws[8];
    if (lane == 31) ws[wid] = inc;
    __syncthreads();
    if (threadIdx.x < 8) {
        int s = ws[threadIdx.x]; int i2 = s;
        #pragma unroll
        for (int o = 1; o < 8; o <<= 1) {
            int n = __shfl_up_sync(0xFFu, i2, o);
            if ((int)threadIdx.x >= o) i2 += n;
        }
        ws[threadIdx.x] = i2 - s;
    }
    __syncthreads();
    int r = inc - v + ws[wid];
    __syncthreads();
    return r;
}

// For e>0: larger e -> smaller bin. bin in [0, 32768).
__device__ __forceinline__ unsigned binOf(float e) {
    return (0x7FFFFFFFu - __float_as_uint(e)) >> 16;
}

// ---------------- kernels ----------------------------------------------------
__global__ void k_init() {
    int t = threadIdx.x;
    if (t < NB) { g_pt[t] = 0.0; g_pd[t] = 0.0; g_gts[t] = 0.0; g_lov[t] = 0.0; }
    if (t == NB) { g_bce = 0.0; g_bnd = 0.0; }
}

// Fused: BCE + boundary BCE + Dice sums + per-bin Lovasz accumulators (RED.v2).
// Each thread owns 16 CONTIGUOUS pixels (one row span); stencil via float4 loads.
__global__ __launch_bounds__(TPB) void k_main(const float* __restrict__ logits,
                                              const float* __restrict__ tgt) {
    int blk = blockIdx.x, t = threadIdx.x;
    int seg = blk >> 6;
    int base = blk * BLK_ITEMS;
    float* acc = g_acc + seg * (NBINS*4);

    float aB = 0.f, aW = 0.f, aPt = 0.f, aPd = 0.f, aY = 0.f;

    int q0 = base + t * 16;           // first pixel of this thread (global index)
    int pos0 = q0 - seg * SEG;
    int h = pos0 >> 9;
    int w0 = pos0 & 511;
    bool hasTop = (h > 0), hasBot = (h < Hd - 1);

    const float4* lg4 = (const float4*)logits;
    const float4* tg4 = (const float4*)tgt;

    #pragma unroll
    for (int c = 0; c < 4; c++) {
        int p = q0 + c * 4;
        int w = w0 + c * 4;
        float4 lx = lg4[p >> 2];

        float rv[3][6];
        #pragma unroll
        for (int r = 0; r < 3; r++) {
            int dr = r - 1;
            bool rowok = (dr == 0) || (dr < 0 ? hasTop : hasBot);
            int rp = p + dr * Wd;
            float4 cv = rowok ? tg4[rp >> 2] : make_float4(0.f, 0.f, 0.f, 0.f);
            rv[r][1] = cv.x; rv[r][2] = cv.y; rv[r][3] = cv.z; rv[r][4] = cv.w;
            rv[r][0] = (rowok && w > 0)        ? __ldg(&tgt[rp - 1]) : 0.f;
            rv[r][5] = (rowok && w + 4 < Wd)   ? __ldg(&tgt[rp + 4]) : 0.f;
        }

        float xs[4] = {lx.x, lx.y, lx.z, lx.w};
        #pragma unroll
        for (int i = 0; i < 4; i++) {
            float x = xs[i];
            float y = rv[1][i + 1];
            float ax = fabsf(x);
            float bce = fmaxf(x, 0.f) - x * y + log1pf(expf(-ax));
            float pr = 1.f / (1.f + expf(-x));
            float cnt = rv[0][i] + rv[0][i+1] + rv[0][i+2]
                      + rv[1][i] + rv[1][i+1] + rv[1][i+2]
                      + rv[2][i] + rv[2][i+1] + rv[2][i+2];
            float wt = (cnt > 0.5f && cnt < 8.5f) ? 3.0f : 1.0f;

            aB += bce; aW += bce * wt; aPt += pr * y; aPd += pr + y; aY += y;

            float e = fmaf(-x, 2.f*y - 1.f, 1.f);   // 1 - x*sign
            if (e > 0.f) {                           // e<=0: relu kills it; sits after all e>0
                unsigned bin = binOf(e);
                int slot = (y > 0.5f) ? 0 : 2;       // {cntPos,sumPos} or {cntNeg,sumNeg}
                atomicAdd((float2*)&acc[bin*4 + slot], make_float2(1.f, e));
            }
        }
    }

    float r;
    r = blockReduceF(aB);  if (t == 0) atomicAdd(&g_bce, (double)r);
    r = blockReduceF(aW);  if (t == 0) atomicAdd(&g_bnd, (double)r);
    r = blockReduceF(aPt); if (t == 0) atomicAdd(&g_pt[seg], (double)r);
    r = blockReduceF(aPd); if (t == 0) atomicAdd(&g_pd[seg], (double)r);
    r = blockReduceF(aY);  if (t == 0) atomicAdd(&g_gts[seg], (double)r);
}

// Per image: prefix-scan bins in descending-e order (ascending bin index) and
// apply the closed-form per-bin Lovasz contribution:
//   positives (first in bin): grad = 1/U0 each -> sumPos / U0            (exact)
//   negatives (after):       telescoping sum -> sumNeg*rem/(U0*(U0+nn))
// where U0 = gts + r0 - P0, rem = gts - P0 - p.
// Also restores g_acc to zero for the next graph replay.
__global__ __launch_bounds__(TPB) void k_bins() {
    int seg = blockIdx.x, t = threadIdx.x;
    float4* a4 = (float4*)(g_acc + seg * (NBINS*4)) + t * BINS_PER_T;

    // pass A: local totals
    int nLoc = 0, pLoc = 0;
    #pragma unroll 8
    for (int q = 0; q < BINS_PER_T; q++) {
        float4 v = a4[q];
        pLoc += (int)v.x;
        nLoc += (int)v.x + (int)v.z;
    }
    int r0 = blockExclScanI(nLoc);   // rank prefix (elements before my first bin)
    int P0 = blockExclScanI(pLoc);   // positive prefix

    float gts = (float)g_gts[seg];
    float contrib = 0.f;

    // pass B: contributions + zero-restore
    #pragma unroll 4
    for (int q = 0; q < BINS_PER_T; q++) {
        float4 v = a4[q];
        int p  = (int)v.x;
        int nn = (int)v.z;
        if (p | nn) {
            float U0 = gts + (float)(r0 - P0);
            if (p) contrib += v.y / U0;
            if (nn) {
                float rem = gts - (float)(P0 + p);
                if (rem > 0.f) contrib += v.w * rem / (U0 * (U0 + (float)nn));
            }
            r0 += p + nn;
            P0 += p;
            a4[q] = make_float4(0.f, 0.f, 0.f, 0.f);
        }
    }

    float r = blockReduceF(contrib);
    if (t == 0) g_lov[seg] = (double)r;
}

__global__ void k_final(float* out, int out_size) {
    if (threadIdx.x == 0 && blockIdx.x == 0) {
        double dice = 0.0;
        for (int b = 0; b < NB; b++) dice += (2.0 * g_pt[b]) / (g_pd[b] + 1e-7);
        double lov = 0.0;
        for (int b = 0; b < NB; b++) lov += g_lov[b];
        double loss = 0.3 * (g_bce / (double)NTOT)
                    + 0.3 * (1.0 - dice / (double)NB)
                    + 0.2 * (g_bnd / (double)NTOT)
                    + 0.2 * (lov / (double)NB);
        for (int i = 0; i < out_size; i++) out[i] = (float)loss;
    }
}

// ---------------- launch ------------------------------------------------------
extern "C" void kernel_launch(void* const* d_in, const int* in_sizes, int n_in,
                              void* d_out, int out_size) {
    const float* logits = (const float*)d_in[0];
    const float* tgt    = (const float*)d_in[1];
    float* out = (float*)d_out;

    k_init<<<1, 64>>>();
    k_main<<<NBLOCKS, TPB>>>(logits, tgt);
    k_bins<<<NB, TPB>>>();
    k_final<<<1, 32>>>(out, out_size);
}

// round 16
// speedup vs baseline: 2.5215x; 1.2561x over previous
#include <cuda_runtime.h>
#include <math.h>

#define NB 32
#define Wd 512
#define Hd 512
#define SEG (Hd*Wd)              // 262144 per image
#define NTOT (NB*SEG)            // 8388608
#define TPB 256
#define IPT 16
#define BLK_ITEMS (TPB*IPT)      // 4096
#define NBLOCKS (NTOT/BLK_ITEMS) // 2048
#define NBINS 32768              // top-15 bins of positive-e floats
#define BTPB 1024                // k_bins block size
#define BINS_PER_T (NBINS/BTPB)  // 32

// ---------------- scratch (static device globals; no allocation) -------------
// per-image, per-bin: {cntPos, sumEpos, cntNeg, sumEneg}  (16 MB total)
// zero at module load; k_bins restores zeros after reading (graph-replay safe).
__device__ float g_acc[NB*NBINS*4];
__device__ double g_bce, g_edge;
__device__ double g_pt[NB], g_pr[NB], g_gts[NB];
__device__ double g_lov[NB];

// ---------------- helpers ----------------------------------------------------
__device__ __forceinline__ float warpReduceF(float v) {
    #pragma unroll
    for (int o = 16; o; o >>= 1) v += __shfl_down_sync(0xFFFFFFFFu, v, o);
    return v;
}

__device__ __forceinline__ float blockReduceF(float v) {
    __shared__ float s[8];
    int lane = threadIdx.x & 31, wid = threadIdx.x >> 5;
    v = warpReduceF(v);
    if (lane == 0) s[wid] = v;
    __syncthreads();
    v = (threadIdx.x < 8) ? s[threadIdx.x] : 0.f;
    if (wid == 0) v = warpReduceF(v);
    __syncthreads();
    return v;  // valid on thread 0
}

// exclusive scan over a block of up to 1024 threads (one int per thread)
__device__ __forceinline__ int blockExclScan1024(int v) {
    int lane = threadIdx.x & 31, wid = threadIdx.x >> 5;
    int inc = v;
    #pragma unroll
    for (int o = 1; o < 32; o <<= 1) {
        int n = __shfl_up_sync(0xFFFFFFFFu, inc, o);
        if (lane >= o) inc += n;
    }
    __shared__ int ws[32];
    if (lane == 31) ws[wid] = inc;
    __syncthreads();
    if (threadIdx.x < 32) {
        int s = ws[threadIdx.x]; int i2 = s;
        #pragma unroll
        for (int o = 1; o < 32; o <<= 1) {
            int n = __shfl_up_sync(0xFFFFFFFFu, i2, o);
            if (lane >= o) i2 += n;
        }
        ws[threadIdx.x] = i2 - s;
    }
    __syncthreads();
    int r = inc - v + ws[wid];
    __syncthreads();
    return r;
}

// For e>0: larger e -> smaller bin. bin in [0, 32768).
__device__ __forceinline__ unsigned binOf(float e) {
    return (0x7FFFFFFFu - __float_as_uint(e)) >> 16;
}

// ---------------- kernels ----------------------------------------------------
__global__ void k_init() {
    int t = threadIdx.x;
    if (t < NB) { g_pt[t] = 0.0; g_pr[t] = 0.0; g_gts[t] = 0.0; g_lov[t] = 0.0; }
    if (t == NB) { g_bce = 0.0; g_edge = 0.0; }
}

// Fused: BCE + edge-BCE + Dice sums + per-bin Lovasz accumulators (RED.v2).
// Each thread owns 16 CONTIGUOUS pixels (one row span); stencil via float4 loads.
__global__ __launch_bounds__(TPB) void k_main(const float* __restrict__ logits,
                                              const float* __restrict__ tgt) {
    int blk = blockIdx.x, t = threadIdx.x;
    int seg = blk >> 6;
    int base = blk * BLK_ITEMS;
    float* acc = g_acc + seg * (NBINS*4);

    float aB = 0.f, aE = 0.f, aPt = 0.f, aPr = 0.f, aY = 0.f;

    int q0 = base + t * 16;           // first pixel of this thread (global index)
    int pos0 = q0 - seg * SEG;
    int h = pos0 >> 9;
    int w0 = pos0 & 511;
    bool hasTop = (h > 0), hasBot = (h < Hd - 1);

    const float4* lg4 = (const float4*)logits;
    const float4* tg4 = (const float4*)tgt;

    #pragma unroll
    for (int c = 0; c < 4; c++) {
        int p = q0 + c * 4;
        int w = w0 + c * 4;
        float4 lx = lg4[p >> 2];

        float rv[3][6];
        #pragma unroll
        for (int r = 0; r < 3; r++) {
            int dr = r - 1;
            bool rowok = (dr == 0) || (dr < 0 ? hasTop : hasBot);
            int rp = p + dr * Wd;
            float4 cv = rowok ? tg4[rp >> 2] : make_float4(0.f, 0.f, 0.f, 0.f);
            rv[r][1] = cv.x; rv[r][2] = cv.y; rv[r][3] = cv.z; rv[r][4] = cv.w;
            rv[r][0] = (rowok && w > 0)        ? __ldg(&tgt[rp - 1]) : 0.f;
            rv[r][5] = (rowok && w + 4 < Wd)   ? __ldg(&tgt[rp + 4]) : 0.f;
        }

        // shared column sums for the 3x3 stencil
        float cs[6];
        #pragma unroll
        for (int j = 0; j < 6; j++) cs[j] = rv[0][j] + rv[1][j] + rv[2][j];

        float xs[4] = {lx.x, lx.y, lx.z, lx.w};
        #pragma unroll
        for (int i = 0; i < 4; i++) {
            float x = xs[i];
            float y = rv[1][i + 1];
            float ax = fabsf(x);

            float tt = __expf(-ax);              // exp(-|x|), in (0,1]
            float s1 = 1.f + tt;
            float lg = __logf(s1);               // == log1p(exp(-|x|)) to ~1e-7
            float inv = __fdividef(1.f, s1);     // sigmoid(|x|)
            float pr = (x >= 0.f) ? inv : (1.f - inv);
            float bce = fmaxf(x, 0.f) - x * y + lg;

            float cnt = cs[i] + cs[i+1] + cs[i+2];
            bool edge = (cnt > 0.5f && cnt < 8.5f);

            aB += bce;
            aE += edge ? bce : 0.f;
            aPt += (y > 0.5f) ? pr : 0.f;
            aPr += pr;
            aY += y;

            float e = fmaf(-x, 2.f*y - 1.f, 1.f);   // 1 - x*sign
            if (e > 0.f) {                           // e<=0: relu kills it
                unsigned bin = binOf(e);
                int slot = (y > 0.5f) ? 0 : 2;       // {cntPos,sumPos} or {cntNeg,sumNeg}
                atomicAdd((float2*)&acc[bin*4 + slot], make_float2(1.f, e));
            }
        }
    }

    float r;
    r = blockReduceF(aB);  if (t == 0) atomicAdd(&g_bce, (double)r);
    r = blockReduceF(aE);  if (t == 0) atomicAdd(&g_edge, (double)r);
    r = blockReduceF(aPt); if (t == 0) atomicAdd(&g_pt[seg], (double)r);
    r = blockReduceF(aPr); if (t == 0) atomicAdd(&g_pr[seg], (double)r);
    r = blockReduceF(aY);  if (t == 0) atomicAdd(&g_gts[seg], (double)r);
}

// Per image: prefix-scan bins in descending-e order (ascending bin index) and
// apply the closed-form per-bin Lovasz contribution:
//   positives (first in bin): grad = 1/U0 each -> sumPos / U0            (exact)
//   negatives (after):       telescoping sum -> sumNeg*rem/(U0*(U0+nn))
// where U0 = gts + r0 - P0, rem = gts - P0 - p.
// Also restores g_acc to zero for the next graph replay.
__global__ __launch_bounds__(BTPB) void k_bins() {
    int seg = blockIdx.x, t = threadIdx.x;
    float4* a4 = (float4*)(g_acc + seg * (NBINS*4)) + t * BINS_PER_T;

    // pass A: local totals
    int nLoc = 0, pLoc = 0;
    float4 vv[BINS_PER_T];
    #pragma unroll
    for (int q = 0; q < BINS_PER_T; q++) {
        vv[q] = a4[q];
        pLoc += (int)vv[q].x;
        nLoc += (int)vv[q].x + (int)vv[q].z;
    }
    int r0 = blockExclScan1024(nLoc);   // rank prefix
    int P0 = blockExclScan1024(pLoc);   // positive prefix

    float gts = (float)g_gts[seg];
    float contrib = 0.f;

    // pass B: contributions + zero-restore
    #pragma unroll
    for (int q = 0; q < BINS_PER_T; q++) {
        float4 v = vv[q];
        int p  = (int)v.x;
        int nn = (int)v.z;
        if (p | nn) {
            float U0 = gts + (float)(r0 - P0);
            if (p) contrib += v.y / U0;
            if (nn) {
                float rem = gts - (float)(P0 + p);
                if (rem > 0.f) contrib += v.w * rem / (U0 * (U0 + (float)nn));
            }
            r0 += p + nn;
            P0 += p;
            a4[q] = make_float4(0.f, 0.f, 0.f, 0.f);
        }
    }

    // block reduce (up to 32 warps)
    __shared__ float sred[32];
    int lane = t & 31, wid = t >> 5;
    contrib = warpReduceF(contrib);
    if (lane == 0) sred[wid] = contrib;
    __syncthreads();
    if (t < 32) {
        float v2 = sred[t];
        v2 = warpReduceF(v2);
        if (t == 0) g_lov[seg] = (double)v2;
    }
}

__global__ void k_final(float* out, int out_size) {
    int t = threadIdx.x;
    double dice = 0.0, lov = 0.0;
    if (t < NB) {
        dice = (2.0 * g_pt[t]) / (g_pr[t] + g_gts[t] + 1e-7);
        lov = g_lov[t];
    }
    #pragma unroll
    for (int o = 16; o; o >>= 1) {
        dice += __shfl_down_sync(0xFFFFFFFFu, dice, o);
        lov  += __shfl_down_sync(0xFFFFFFFFu, lov, o);
    }
    if (t == 0) {
        double bce = g_bce, edge = g_edge;
        double bnd = bce + 2.0 * edge;           // wt=3 on edges == bce + 2*edge_bce
        double loss = 0.3 * (bce / (double)NTOT)
                    + 0.3 * (1.0 - dice / (double)NB)
                    + 0.2 * (bnd / (double)NTOT)
                    + 0.2 * (lov / (double)NB);
        for (int i = 0; i < out_size; i++) out[i] = (float)loss;
    }
}

// ---------------- launch ------------------------------------------------------
extern "C" void kernel_launch(void* const* d_in, const int* in_sizes, int n_in,
                              void* d_out, int out_size) {
    const float* logits = (const float*)d_in[0];
    const float* tgt    = (const float*)d_in[1];
    float* out = (float*)d_out;

    k_init<<<1, 64>>>();
    k_main<<<NBLOCKS, TPB>>>(logits, tgt);
    k_bins<<<NB, BTPB>>>();
    k_final<<<1, 32>>>(out, out_size);
}